// round 7
// baseline (speedup 1.0000x reference)
#include <cuda_runtime.h>
#include <cstdint>

// HybridLoss: smooth_l1(preds,targets) + 0.5*(1 - mean(box_overlap))
// preds, targets: [2000000, 10] float32 row-major. Output: 1 float scalar.
//
// Bulk-async (cp.async.bulk -> UBLKCP) double-buffered smem pipeline:
// thread 0 issues 2x10KB contiguous copies per stage with mbarrier
// complete_tx; all 256 threads consume rows from smem. 5 CTAs/SM.

#define NROWS 2000000
#define THREADS 256
#define NBLOCKS 740                                   // 148 SMs * 5 CTAs
#define TILE_ROWS 256
#define TILE_BYTES (TILE_ROWS * 40)                   // 10240 B per array
#define NTILES ((NROWS + TILE_ROWS - 1) / TILE_ROWS)  // 7813 (last tile 128 rows)
#define EPSF 1e-6f

__device__ double g_acc[2] = {0.0, 0.0};
__device__ unsigned int g_ticket = 0;

__device__ __forceinline__ uint32_t smem_u32(const void* p) {
    return (uint32_t)__cvta_generic_to_shared(p);
}

__device__ __forceinline__ void mbar_init(uint32_t mbar, uint32_t count) {
    asm volatile("mbarrier.init.shared.b64 [%0], %1;" :: "r"(mbar), "r"(count) : "memory");
}
__device__ __forceinline__ void mbar_expect_tx(uint32_t mbar, uint32_t bytes) {
    asm volatile("mbarrier.arrive.expect_tx.shared.b64 _, [%0], %1;" :: "r"(mbar), "r"(bytes) : "memory");
}
__device__ __forceinline__ void bulk_g2s(uint32_t dst, const void* src, uint32_t bytes, uint32_t mbar) {
    asm volatile(
        "cp.async.bulk.shared::cta.global.mbarrier::complete_tx::bytes [%0], [%1], %2, [%3];"
        :: "r"(dst), "l"(src), "r"(bytes), "r"(mbar) : "memory");
}
__device__ __forceinline__ void mbar_wait(uint32_t mbar, uint32_t parity) {
    uint32_t done;
    asm volatile(
        "{\n\t.reg .pred p;\n\t"
        "mbarrier.try_wait.parity.acquire.cta.shared::cta.b64 p, [%1], %2;\n\t"
        "selp.b32 %0, 1, 0, p;\n\t}"
        : "=r"(done) : "r"(mbar), "r"(parity) : "memory");
    if (!done) {
        asm volatile(
            "{\n\t.reg .pred P1;\n\t"
            "WAIT_LOOP_%=:\n\t"
            "mbarrier.try_wait.parity.acquire.cta.shared::cta.b64 P1, [%0], %1, 0x989680;\n\t"
            "@P1 bra.uni WAIT_DONE_%=;\n\t"
            "bra.uni WAIT_LOOP_%=;\n\t"
            "WAIT_DONE_%=:\n\t}"
            :: "r"(mbar), "r"(parity) : "memory");
    }
}

__device__ __forceinline__ void row_math(const char* __restrict__ prow,
                                         const char* __restrict__ trow,
                                         float& l1_acc, float& ov_acc)
{
    float p[10], t[10];
    const float2* rp = reinterpret_cast<const float2*>(prow);
    const float2* rt = reinterpret_cast<const float2*>(trow);
    #pragma unroll
    for (int j = 0; j < 5; j++) {
        float2 a = rp[j]; p[2*j] = a.x; p[2*j+1] = a.y;
        float2 b = rt[j]; t[2*j] = b.x; t[2*j+1] = b.y;
    }

    // ---- smooth L1, select-free ----
    #pragma unroll
    for (int j = 0; j < 10; j++) {
        float d  = p[j] - t[j];
        float ad = fabsf(d);
        float m  = fminf(ad, 1.0f);
        l1_acc = fmaf(m, fmaf(-0.5f, m, ad), l1_acc);
    }

    // ---- raw quaternions (no normalization) ----
    const float px = p[6], py = p[7], pz = p[8], pw = p[9];
    const float gx = t[6], gy = t[7], gz = t[8], gw = t[9];
    const float Ap = px*px + py*py + pz*pz + pw*pw;
    const float Ag = gx*gx + gy*gy + gz*gz + gw*gw;
    const float rpg = __fdividef(1.0f, Ap * Ag);
    const float sp  = 0.5f * Ag * rpg;   // 0.5/Ap
    const float sg  = 0.5f * Ap * rpg;   // 0.5/Ag

    const float dq = px*gx + py*gy + pz*gz + pw*gw;
    const float rot_align = fmaxf(fmaf(4.0f * dq * dq, rpg, -1.0f) * (1.0f/3.0f), 0.0f);

    const float dpx = p[3], dpy = p[4], dpz = p[5];
    const float dgx = t[3], dgy = t[4], dgz = t[5];

    float num = 1.0f, den = 1.0f;
    {
        float mp = (Ap - 2.0f*(py*py + pz*pz))*dpx + 2.0f*(px*py + pz*pw)*dpy + 2.0f*(px*pz - py*pw)*dpz;
        float mg = (Ag - 2.0f*(gy*gy + gz*gz))*dgx + 2.0f*(gx*gy + gz*gw)*dgy + 2.0f*(gx*gz - gy*gw)*dgz;
        float pe = sp * fabsf(mp), ge = sg * fabsf(mg);
        float cd = fabsf(p[0] - t[0]);
        num *= fmaxf(2.0f * fminf(pe, ge) - cd, 0.0f);
        den *= pe + ge + EPSF;
    }
    {
        float mp = 2.0f*(px*py - pz*pw)*dpx + (Ap - 2.0f*(px*px + pz*pz))*dpy + 2.0f*(py*pz + px*pw)*dpz;
        float mg = 2.0f*(gx*gy - gz*gw)*dgx + (Ag - 2.0f*(gx*gx + gz*gz))*dgy + 2.0f*(gy*gz + gx*gw)*dgz;
        float pe = sp * fabsf(mp), ge = sg * fabsf(mg);
        float cd = fabsf(p[1] - t[1]);
        num *= fmaxf(2.0f * fminf(pe, ge) - cd, 0.0f);
        den *= pe + ge + EPSF;
    }
    {
        float mp = 2.0f*(px*pz + py*pw)*dpx + 2.0f*(py*pz - px*pw)*dpy + (Ap - 2.0f*(px*px + py*py))*dpz;
        float mg = 2.0f*(gx*gz + gy*gw)*dgx + 2.0f*(gy*gz - gx*gw)*dgy + (Ag - 2.0f*(gx*gx + gy*gy))*dgz;
        float pe = sp * fabsf(mp), ge = sg * fabsf(mg);
        float cd = fabsf(p[2] - t[2]);
        num *= fmaxf(2.0f * fminf(pe, ge) - cd, 0.0f);
        den *= pe + ge + EPSF;
    }
    ov_acc += __fdividef(num * rot_align, den);
}

__global__ __launch_bounds__(THREADS, 5) void hl_fused_kernel(
    const float* __restrict__ preds,
    const float* __restrict__ targets,
    float* __restrict__ out)
{
    __shared__ alignas(16) char bufp[2][TILE_BYTES];
    __shared__ alignas(16) char buft[2][TILE_BYTES];
    __shared__ alignas(8)  unsigned long long mbar_s[2];

    const int tid = threadIdx.x;
    const uint32_t mb0 = smem_u32(&mbar_s[0]);
    const uint32_t mb1 = smem_u32(&mbar_s[1]);

    if (tid == 0) {
        mbar_init(mb0, 1);
        mbar_init(mb1, 1);
    }
    __syncthreads();

    // prologue: issue loads for first two tiles
    if (tid == 0) {
        int t0 = blockIdx.x;
        if (t0 < NTILES) {
            uint32_t bytes = (uint32_t)(min(TILE_ROWS, NROWS - t0 * TILE_ROWS) * 40);
            mbar_expect_tx(mb0, bytes * 2);
            bulk_g2s(smem_u32(bufp[0]), (const char*)preds   + (size_t)t0 * TILE_BYTES, bytes, mb0);
            bulk_g2s(smem_u32(buft[0]), (const char*)targets + (size_t)t0 * TILE_BYTES, bytes, mb0);
        }
        int t1 = blockIdx.x + NBLOCKS;
        if (t1 < NTILES) {
            uint32_t bytes = (uint32_t)(min(TILE_ROWS, NROWS - t1 * TILE_ROWS) * 40);
            mbar_expect_tx(mb1, bytes * 2);
            bulk_g2s(smem_u32(bufp[1]), (const char*)preds   + (size_t)t1 * TILE_BYTES, bytes, mb1);
            bulk_g2s(smem_u32(buft[1]), (const char*)targets + (size_t)t1 * TILE_BYTES, bytes, mb1);
        }
    }

    float l1_sum = 0.0f;
    float ov     = 0.0f;

    int it = 0;
    for (int tile = blockIdx.x; tile < NTILES; tile += NBLOCKS, it++) {
        const int s = it & 1;
        const uint32_t parity = (it >> 1) & 1;
        const uint32_t mb = s ? mb1 : mb0;

        mbar_wait(mb, parity);

        const int rows = min(TILE_ROWS, NROWS - tile * TILE_ROWS);
        if (tid < rows)
            row_math(bufp[s] + tid * 40, buft[s] + tid * 40, l1_sum, ov);

        __syncthreads();   // all consumers done with stage s

        // refill stage s with tile it+2
        if (tid == 0) {
            int tn = tile + 2 * NBLOCKS;
            if (tn < NTILES) {
                uint32_t bytes = (uint32_t)(min(TILE_ROWS, NROWS - tn * TILE_ROWS) * 40);
                mbar_expect_tx(mb, bytes * 2);
                bulk_g2s(smem_u32(bufp[s]), (const char*)preds   + (size_t)tn * TILE_BYTES, bytes, mb);
                bulk_g2s(smem_u32(buft[s]), (const char*)targets + (size_t)tn * TILE_BYTES, bytes, mb);
            }
        }
    }

    // ---- block reduction ----
    #pragma unroll
    for (int off = 16; off > 0; off >>= 1) {
        l1_sum += __shfl_down_sync(0xFFFFFFFFu, l1_sum, off);
        ov     += __shfl_down_sync(0xFFFFFFFFu, ov, off);
    }
    __shared__ float warp_l1[THREADS / 32];
    __shared__ float warp_ov[THREADS / 32];
    const int lane = tid & 31;
    const int wid  = tid >> 5;
    if (lane == 0) { warp_l1[wid] = l1_sum; warp_ov[wid] = ov; }
    __syncthreads();

    if (wid == 0) {
        float a = (lane < THREADS / 32) ? warp_l1[lane] : 0.0f;
        float b = (lane < THREADS / 32) ? warp_ov[lane] : 0.0f;
        #pragma unroll
        for (int off = 4; off > 0; off >>= 1) {
            a += __shfl_down_sync(0xFFFFFFFFu, a, off);
            b += __shfl_down_sync(0xFFFFFFFFu, b, off);
        }
        if (lane == 0) {
            atomicAdd(&g_acc[0], (double)a);
            atomicAdd(&g_acc[1], (double)b);
            __threadfence();
            unsigned int ticket = atomicAdd(&g_ticket, 1u);
            if (ticket == (unsigned int)(NBLOCKS - 1)) {
                double s0 = *((volatile double*)&g_acc[0]);
                double s1 = *((volatile double*)&g_acc[1]);
                double param_loss = s0 / ((double)NROWS * 10.0);
                double mean_ov    = s1 / (double)NROWS;
                out[0] = (float)(param_loss + 0.5 * (1.0 - mean_ov));
                *((volatile double*)&g_acc[0]) = 0.0;
                *((volatile double*)&g_acc[1]) = 0.0;
                __threadfence();
                g_ticket = 0;
                __threadfence();
            }
        }
    }
}

extern "C" void kernel_launch(void* const* d_in, const int* in_sizes, int n_in,
                              void* d_out, int out_size) {
    const float* preds   = (const float*)d_in[0];
    const float* targets = (const float*)d_in[1];
    float* out = (float*)d_out;

    hl_fused_kernel<<<NBLOCKS, THREADS>>>(preds, targets, out);
}